// round 1
// baseline (speedup 1.0000x reference)
#include <cuda_runtime.h>

#define U_CNT   100000
#define I_CNT   50000
#define D_DIM   64
#define E_CNT   600000
#define TWOE    (2 * E_CNT)          // 1,200,000
#define N_NODES (U_CNT + I_CNT)      // 150,000
#define ND      (N_NODES * D_DIM)    // 9,600,000

#define SCAN_BS     1024
#define SCAN_BLOCKS ((N_NODES + SCAN_BS - 1) / SCAN_BS)   // 147

struct EdgeRec { int src; float val; };

// ---- scratch (device globals: allocation-free contract) ----
__device__ float   g_ego0[ND];
__device__ float   g_ego1[ND];
__device__ float   g_acc[ND];
__device__ int     g_deg[N_NODES];
__device__ int     g_rowptr[N_NODES + 1];
__device__ int     g_cursor[N_NODES];
__device__ int     g_blocksums[SCAN_BLOCKS];
__device__ EdgeRec g_csr[TWOE];

// ---- 1. init ego0 = concat(user_emb, item_emb); zero degree histogram ----
__global__ void k_init(const float* __restrict__ ue, const float* __restrict__ ie) {
    int i = blockIdx.x * blockDim.x + threadIdx.x;
    if (i < ND)
        g_ego0[i] = (i < U_CNT * D_DIM) ? ue[i] : ie[i - U_CNT * D_DIM];
    if (i < N_NODES)
        g_deg[i] = 0;
}

// ---- 2. degree histogram over destinations ----
__global__ void k_count(const int* __restrict__ dst) {
    int e = blockIdx.x * blockDim.x + threadIdx.x;
    if (e < TWOE)
        atomicAdd(&g_deg[dst[e]], 1);
}

// ---- 3. exclusive scan (3 kernels) ----
__global__ void k_scan1() {
    __shared__ int sh[SCAN_BS];
    int tid = threadIdx.x;
    int idx = blockIdx.x * SCAN_BS + tid;
    int v = (idx < N_NODES) ? g_deg[idx] : 0;
    sh[tid] = v;
    __syncthreads();
    for (int off = 1; off < SCAN_BS; off <<= 1) {
        int t = (tid >= off) ? sh[tid - off] : 0;
        __syncthreads();
        sh[tid] += t;
        __syncthreads();
    }
    if (idx < N_NODES) g_rowptr[idx] = sh[tid] - v;   // exclusive
    if (tid == SCAN_BS - 1) g_blocksums[blockIdx.x] = sh[SCAN_BS - 1];
}

__global__ void k_scan2() {
    // single thread, 147 elements — negligible
    int acc = 0;
    for (int b = 0; b < SCAN_BLOCKS; ++b) {
        int t = g_blocksums[b];
        g_blocksums[b] = acc;
        acc += t;
    }
}

__global__ void k_scan3() {
    int idx = blockIdx.x * SCAN_BS + threadIdx.x;
    if (idx < N_NODES) {
        int r = g_rowptr[idx] + g_blocksums[blockIdx.x];
        g_rowptr[idx] = r;
        g_cursor[idx] = r;
    }
    if (idx == 0) g_rowptr[N_NODES] = TWOE;
}

// ---- 4. bucket fill: CSR edge records, packed 8B {src, val} ----
__global__ void k_fill(const int* __restrict__ src, const int* __restrict__ dst,
                       const float* __restrict__ val) {
    int e = blockIdx.x * blockDim.x + threadIdx.x;
    if (e < TWOE) {
        int d   = dst[e];
        int pos = atomicAdd(&g_cursor[d], 1);
        EdgeRec r;
        r.src = src[e];
        r.val = val[e];
        g_csr[pos] = r;
    }
}

// ---- 5. pull-SpMM: one warp per destination node, fused acc / output ----
// LAYER 0: ego1 = A@ego0;              acc  = ego1
// LAYER 1: ego0 = A@ego1;              acc += ego0
// LAYER 2: x    = A@ego0;              out  = (acc + x) / 3
template <int LAYER>
__global__ void __launch_bounds__(256) k_spmm(float* __restrict__ out) {
    const float* __restrict__ ego_in  = (LAYER == 1) ? g_ego1 : g_ego0;
    float*       __restrict__ ego_out = (LAYER == 0) ? g_ego1 : g_ego0;

    int warp = threadIdx.x >> 5;
    int lane = threadIdx.x & 31;
    int n = blockIdx.x * (blockDim.x >> 5) + warp;
    if (n >= N_NODES) return;

    int beg = g_rowptr[n];
    int end = g_rowptr[n + 1];

    float sx = 0.0f, sy = 0.0f;
    for (int p = beg; p < end; ++p) {
        EdgeRec r = g_csr[p];                       // 8B broadcast load
        const float2 x = *reinterpret_cast<const float2*>(
            &ego_in[(size_t)r.src * D_DIM + lane * 2]);   // 256B coalesced gather
        sx = fmaf(r.val, x.x, sx);
        sy = fmaf(r.val, x.y, sy);
    }

    int base = n * D_DIM + lane * 2;
    if (LAYER == 0) {
        *reinterpret_cast<float2*>(&ego_out[base]) = make_float2(sx, sy);
        *reinterpret_cast<float2*>(&g_acc[base])   = make_float2(sx, sy);
    } else if (LAYER == 1) {
        float2 a = *reinterpret_cast<const float2*>(&g_acc[base]);
        a.x += sx; a.y += sy;
        *reinterpret_cast<float2*>(&ego_out[base]) = make_float2(sx, sy);
        *reinterpret_cast<float2*>(&g_acc[base])   = a;
    } else {
        float2 a = *reinterpret_cast<const float2*>(&g_acc[base]);
        const float inv3 = 1.0f / 3.0f;
        a.x = (a.x + sx) * inv3;
        a.y = (a.y + sy) * inv3;
        *reinterpret_cast<float2*>(&out[base]) = a;
    }
}

extern "C" void kernel_launch(void* const* d_in, const int* in_sizes, int n_in,
                              void* d_out, int out_size) {
    const float* ue  = (const float*)d_in[0];
    const float* ie  = (const float*)d_in[1];
    const int*   src = (const int*)d_in[2];
    const int*   dst = (const int*)d_in[3];
    const float* val = (const float*)d_in[4];
    float* out = (float*)d_out;

    (void)in_sizes; (void)n_in; (void)out_size;

    k_init <<<(ND + 255) / 256, 256>>>(ue, ie);
    k_count<<<(TWOE + 255) / 256, 256>>>(dst);
    k_scan1<<<SCAN_BLOCKS, SCAN_BS>>>();
    k_scan2<<<1, 1>>>();
    k_scan3<<<SCAN_BLOCKS, SCAN_BS>>>();
    k_fill <<<(TWOE + 255) / 256, 256>>>(src, dst, val);

    const int warps_per_block = 256 / 32;
    const int spmm_blocks = (N_NODES + warps_per_block - 1) / warps_per_block;
    k_spmm<0><<<spmm_blocks, 256>>>(out);
    k_spmm<1><<<spmm_blocks, 256>>>(out);
    k_spmm<2><<<spmm_blocks, 256>>>(out);
}

// round 2
// speedup vs baseline: 1.2656x; 1.2656x over previous
#include <cuda_runtime.h>

#define U_CNT   100000
#define I_CNT   50000
#define D_DIM   64
#define E_CNT   600000
#define TWOE    (2 * E_CNT)          // 1,200,000
#define N_NODES (U_CNT + I_CNT)      // 150,000
#define ND      (N_NODES * D_DIM)    // 9,600,000

#define SCAN_BS     1024
#define SCAN_BLOCKS ((N_NODES + SCAN_BS - 1) / SCAN_BS)   // 147

struct EdgeRec { int src; float val; };

// ---- scratch (device globals: allocation-free contract) ----
__device__ float   g_ego0[ND];          // layer-2 output
__device__ float   g_ego1[ND];          // layer-1 output
__device__ int     g_deg[N_NODES];
__device__ int     g_rowptr[N_NODES + 1];
__device__ int     g_cursor[N_NODES];
__device__ int     g_blocksums[SCAN_BLOCKS];
__device__ EdgeRec g_csr[TWOE];

// ---- 1. zero degree histogram (concat copy eliminated: layer 0 reads inputs) ----
__global__ void k_init() {
    int i = blockIdx.x * blockDim.x + threadIdx.x;
    if (i < N_NODES) g_deg[i] = 0;
}

// ---- 2. degree histogram over destinations ----
__global__ void k_count(const int* __restrict__ dst) {
    int e = blockIdx.x * blockDim.x + threadIdx.x;
    if (e < TWOE)
        atomicAdd(&g_deg[dst[e]], 1);
}

// ---- 3. exclusive scan (3 kernels; stage 2 now parallel) ----
__global__ void k_scan1() {
    __shared__ int sh[SCAN_BS];
    int tid = threadIdx.x;
    int idx = blockIdx.x * SCAN_BS + tid;
    int v = (idx < N_NODES) ? g_deg[idx] : 0;
    sh[tid] = v;
    __syncthreads();
    for (int off = 1; off < SCAN_BS; off <<= 1) {
        int t = (tid >= off) ? sh[tid - off] : 0;
        __syncthreads();
        sh[tid] += t;
        __syncthreads();
    }
    if (idx < N_NODES) g_rowptr[idx] = sh[tid] - v;   // exclusive
    if (tid == SCAN_BS - 1) g_blocksums[blockIdx.x] = sh[SCAN_BS - 1];
}

// single-block parallel exclusive scan of the 147 block sums
__global__ void k_scan2() {
    __shared__ int sh[256];
    int tid = threadIdx.x;
    int v = (tid < SCAN_BLOCKS) ? g_blocksums[tid] : 0;
    sh[tid] = v;
    __syncthreads();
    for (int off = 1; off < 256; off <<= 1) {
        int t = (tid >= off) ? sh[tid - off] : 0;
        __syncthreads();
        sh[tid] += t;
        __syncthreads();
    }
    if (tid < SCAN_BLOCKS) g_blocksums[tid] = sh[tid] - v;   // exclusive
}

__global__ void k_scan3() {
    int idx = blockIdx.x * SCAN_BS + threadIdx.x;
    if (idx < N_NODES) {
        int r = g_rowptr[idx] + g_blocksums[blockIdx.x];
        g_rowptr[idx] = r;
        g_cursor[idx] = r;
    }
    if (idx == 0) g_rowptr[N_NODES] = TWOE;
}

// ---- 4. bucket fill: CSR edge records, packed 8B {src, val} ----
__global__ void k_fill(const int* __restrict__ src, const int* __restrict__ dst,
                       const float* __restrict__ val) {
    int e = blockIdx.x * blockDim.x + threadIdx.x;
    if (e < TWOE) {
        int d   = dst[e];
        int pos = atomicAdd(&g_cursor[d], 1);
        EdgeRec r;
        r.src = src[e];
        r.val = val[e];
        g_csr[pos] = r;
    }
}

// ---- 5. pull-SpMM: one warp per destination node ----
// LAYER 0: ego1 = A@[ue;ie]   (gathers straight from inputs, no concat buffer)
// LAYER 1: ego0 = A@ego1
// LAYER 2: x    = A@ego0;  out = (ego1 + ego0 + x) / 3   (no acc buffer)
template <int LAYER>
__global__ void __launch_bounds__(256) k_spmm(const float* __restrict__ ue,
                                              const float* __restrict__ ie,
                                              float* __restrict__ out) {
    const float* __restrict__ ego_in  = (LAYER == 1) ? g_ego1 : g_ego0;
    float*       __restrict__ ego_out = (LAYER == 0) ? g_ego1 : g_ego0;

    int warp = threadIdx.x >> 5;
    int lane = threadIdx.x & 31;
    int n = blockIdx.x * (blockDim.x >> 5) + warp;
    if (n >= N_NODES) return;

    int beg = g_rowptr[n];
    int end = g_rowptr[n + 1];

    float sx = 0.0f, sy = 0.0f;
    int lo = lane * 2;
    for (int p = beg; p < end; ++p) {
        EdgeRec r = g_csr[p];                       // 8B broadcast load
        const float* row;
        if (LAYER == 0)
            row = (r.src < U_CNT) ? (ue + (size_t)r.src * D_DIM)
                                  : (ie + (size_t)(r.src - U_CNT) * D_DIM);
        else
            row = ego_in + (size_t)r.src * D_DIM;
        const float2 x = *reinterpret_cast<const float2*>(row + lo);  // 256B coalesced gather
        sx = fmaf(r.val, x.x, sx);
        sy = fmaf(r.val, x.y, sy);
    }

    int base = n * D_DIM + lo;
    if (LAYER != 2) {
        *reinterpret_cast<float2*>(&ego_out[base]) = make_float2(sx, sy);
    } else {
        float2 a = *reinterpret_cast<const float2*>(&g_ego1[base]);   // layer-1 output
        float2 b = *reinterpret_cast<const float2*>(&g_ego0[base]);   // layer-2 output
        const float inv3 = 1.0f / 3.0f;
        a.x = (a.x + b.x + sx) * inv3;
        a.y = (a.y + b.y + sy) * inv3;
        *reinterpret_cast<float2*>(&out[base]) = a;
    }
}

extern "C" void kernel_launch(void* const* d_in, const int* in_sizes, int n_in,
                              void* d_out, int out_size) {
    const float* ue  = (const float*)d_in[0];
    const float* ie  = (const float*)d_in[1];
    const int*   src = (const int*)d_in[2];
    const int*   dst = (const int*)d_in[3];
    const float* val = (const float*)d_in[4];
    float* out = (float*)d_out;

    (void)in_sizes; (void)n_in; (void)out_size;

    k_init <<<(N_NODES + 255) / 256, 256>>>();
    k_count<<<(TWOE + 255) / 256, 256>>>(dst);
    k_scan1<<<SCAN_BLOCKS, SCAN_BS>>>();
    k_scan2<<<1, 256>>>();
    k_scan3<<<SCAN_BLOCKS, SCAN_BS>>>();
    k_fill <<<(TWOE + 255) / 256, 256>>>(src, dst, val);

    const int warps_per_block = 256 / 32;
    const int spmm_blocks = (N_NODES + warps_per_block - 1) / warps_per_block;
    k_spmm<0><<<spmm_blocks, 256>>>(ue, ie, out);
    k_spmm<1><<<spmm_blocks, 256>>>(ue, ie, out);
    k_spmm<2><<<spmm_blocks, 256>>>(ue, ie, out);
}